// round 14
// baseline (speedup 1.0000x reference)
#include <cuda_runtime.h>
#include <cuda_bf16.h>
#include <math.h>
#include <stdint.h>

#define D_MODEL 768
#define N_HEADS 12
#define D_KH    64
#define B_      2
#define S_      2048
#define M_TOT   (B_ * S_)
#define BH_     (B_ * N_HEADS)
#define LN_EPS  1e-5f
#define NELEM   ((size_t)M_TOT * D_MODEL)
#define WELEM   ((size_t)D_MODEL * D_MODEL)

// ---------------- scratch (allocation-free: __device__ globals) ----------------
__device__ uint16_t g_inqh[NELEM], g_inql[NELEM];
__device__ uint16_t g_inkh[NELEM], g_inkl[NELEM];
__device__ uint16_t g_invh[NELEM], g_invl[NELEM];
__device__ uint16_t g_wqh[WELEM], g_wql[WELEM];
__device__ uint16_t g_wkh[WELEM], g_wkl[WELEM];
__device__ uint16_t g_wvh[WELEM], g_wvl[WELEM];
__device__ uint16_t g_woh[WELEM], g_wol[WELEM];
__device__ uint16_t g_Qh[NELEM], g_Ql[NELEM];
__device__ uint16_t g_Kh[NELEM], g_Kl[NELEM];
__device__ uint16_t g_Vh[NELEM], g_Vl[NELEM];
__device__ uint16_t g_Oh[NELEM], g_Ol[NELEM];
__device__ float    g_P[NELEM];
__device__ float    g_rs[(size_t)BH_ * S_];   // softmax row sums (unnormalized)

// ======================= helpers =======================
__device__ __forceinline__ uint32_t smem_u32(const void* p) {
    uint32_t a;
    asm("{ .reg .u64 t; cvta.to.shared.u64 t, %1; cvt.u32.u64 %0, t; }"
        : "=r"(a) : "l"(p));
    return a;
}
__device__ __forceinline__ void ldm_x4(uint32_t* r, uint32_t addr) {
    asm volatile("ldmatrix.sync.aligned.m8n8.x4.shared.b16 {%0,%1,%2,%3}, [%4];"
                 : "=r"(r[0]), "=r"(r[1]), "=r"(r[2]), "=r"(r[3]) : "r"(addr));
}
__device__ __forceinline__ void ldm_x4_trans(uint32_t* r, uint32_t addr) {
    asm volatile("ldmatrix.sync.aligned.m8n8.x4.trans.shared.b16 {%0,%1,%2,%3}, [%4];"
                 : "=r"(r[0]), "=r"(r[1]), "=r"(r[2]), "=r"(r[3]) : "r"(addr));
}
__device__ __forceinline__ void mma_bf16(float* c, const uint32_t* a, const uint32_t* b) {
    asm volatile(
        "mma.sync.aligned.m16n8k16.row.col.f32.bf16.bf16.f32 "
        "{%0,%1,%2,%3}, {%4,%5,%6,%7}, {%8,%9}, {%0,%1,%2,%3};"
        : "+f"(c[0]), "+f"(c[1]), "+f"(c[2]), "+f"(c[3])
        : "r"(a[0]), "r"(a[1]), "r"(a[2]), "r"(a[3]), "r"(b[0]), "r"(b[1]));
}
__device__ __forceinline__ void cp16(uint32_t s, const void* g) {
    asm volatile("cp.async.cg.shared.global [%0], [%1], 16;" :: "r"(s), "l"(g));
}
#define CP_COMMIT() asm volatile("cp.async.commit_group;")
#define CP_WAIT0()  asm volatile("cp.async.wait_group 0;")
#define CP_WAIT1()  asm volatile("cp.async.wait_group 1;")

__device__ __forceinline__ uint32_t pack2(__nv_bfloat16 a, __nv_bfloat16 b) {
    return ((uint32_t)__bfloat16_as_ushort(b) << 16) | (uint32_t)__bfloat16_as_ushort(a);
}
__device__ __forceinline__ void split4(float4 v, uint2& hi, uint2& lo) {
    __nv_bfloat16 h0 = __float2bfloat16(v.x), h1 = __float2bfloat16(v.y);
    __nv_bfloat16 h2 = __float2bfloat16(v.z), h3 = __float2bfloat16(v.w);
    hi = make_uint2(pack2(h0, h1), pack2(h2, h3));
    __nv_bfloat16 l0 = __float2bfloat16(v.x - __bfloat162float(h0));
    __nv_bfloat16 l1 = __float2bfloat16(v.y - __bfloat162float(h1));
    __nv_bfloat16 l2 = __float2bfloat16(v.z - __bfloat162float(h2));
    __nv_bfloat16 l3 = __float2bfloat16(v.w - __bfloat162float(h3));
    lo = make_uint2(pack2(l0, l1), pack2(l2, l3));
}
__device__ __forceinline__ void split2(float x, float y, uint32_t& hi, uint32_t& lo) {
    __nv_bfloat16 h0 = __float2bfloat16(x), h1 = __float2bfloat16(y);
    hi = pack2(h0, h1);
    lo = pack2(__float2bfloat16(x - __bfloat162float(h0)),
               __float2bfloat16(y - __bfloat162float(h1)));
}

// ======================= by-value arg structs (graph-safe) =======================
struct SplitArgs {
    const float4* in[4];
    uint2* hi[4];
    uint2* lo[4];
};
struct Gemm3Args {
    const uint16_t* Ah[3];
    const uint16_t* Al[3];
    const uint16_t* Wh[3];
    const uint16_t* Wl[3];
    const float*    bias[3];
    uint16_t*       Ch[3];
    uint16_t*       Cl[3];
};

// fused split; blockIdx.y == nsplit -> zero the rowsum buffer instead
__global__ void split_fused_kernel(SplitArgs a, int nsplit, float4* rs, int rs_blocks)
{
    const int z = blockIdx.y;
    if (z == nsplit) {
        if (blockIdx.x < rs_blocks)
            rs[blockIdx.x * 256 + threadIdx.x] = make_float4(0.f, 0.f, 0.f, 0.f);
        return;
    }
    int i = blockIdx.x * 256 + threadIdx.x;
    uint2 h, l;
    split4(a.in[z][i], h, l);
    a.hi[z][i] = h; a.lo[z][i] = l;
}

#define LDA  40   // row stride (halves) for 32-wide tiles
#define LDA48 56  // row stride (halves) for 48-wide tiles (112B, conflict-free)
#define LDV  72

// =====================================================================
// GEMM (NT): C = A @ W^T + bias. K-chunk 48 (16 chunks), 2-stage
// cp.async pipeline, split-bf16, B fragments paired via ldmatrix.x4.
// smem: per stage Ah|Al|Wh|Wl 14336 each = 57344; 2 stages = 114688.
// =====================================================================
template<bool FUSED3>
__global__ void __launch_bounds__(256)
gemm_s(Gemm3Args ga,
       const uint16_t* __restrict__ Ahg_, const uint16_t* __restrict__ Alg_,
       const uint16_t* __restrict__ Whg_, const uint16_t* __restrict__ Wlg_,
       const float* __restrict__ bias_, float* __restrict__ Cf)
{
    const uint16_t *Ahg, *Alg, *Whg, *Wlg;
    const float* bias;
    uint16_t *Ch = nullptr, *Cl = nullptr;
    if (FUSED3) {
        const int z = blockIdx.z;
        Ahg = ga.Ah[z]; Alg = ga.Al[z];
        Whg = ga.Wh[z]; Wlg = ga.Wl[z];
        bias = ga.bias[z]; Ch = ga.Ch[z]; Cl = ga.Cl[z];
    } else {
        Ahg = Ahg_; Alg = Alg_; Whg = Whg_; Wlg = Wlg_;
        bias = bias_;
    }

    extern __shared__ __align__(16) char sm[];
    const uint32_t sb = smem_u32(sm);
    const int tid = threadIdx.x, wid = tid >> 5, lane = tid & 31;
    const int m0 = blockIdx.x * 128, n0 = blockIdx.y * 128;
    const int wm = (wid & 1) * 64, wn = (wid >> 1) * 32;

    // per-thread load coords: 6 cp16 per 48-half row, 768 cp16 per array
    const int lr0 = tid / 6, lc0 = (tid % 6) * 8;          // i=0
    const int f1 = tid + 256, lr1 = f1 / 6, lc1 = (f1 % 6) * 8;
    const int f2 = tid + 512, lr2 = f2 / 6, lc2 = (f2 % 6) * 8;

    float acc[4][4][4] = {};
    {
        const uint32_t s0 = sb;
        #define LD_CHUNK(stbase, kk0)                                           \
        {                                                                       \
            uint32_t so; size_t ga2, gb;                                        \
            so = (stbase) + (uint32_t)(lr0 * LDA48 + lc0) * 2;                  \
            ga2 = (size_t)(m0 + lr0) * 768 + (kk0) + lc0;                       \
            gb  = (size_t)(n0 + lr0) * 768 + (kk0) + lc0;                       \
            cp16(so, Ahg + ga2); cp16(so + 14336u, Alg + ga2);                  \
            cp16(so + 28672u, Whg + gb); cp16(so + 43008u, Wlg + gb);           \
            so = (stbase) + (uint32_t)(lr1 * LDA48 + lc1) * 2;                  \
            ga2 = (size_t)(m0 + lr1) * 768 + (kk0) + lc1;                       \
            gb  = (size_t)(n0 + lr1) * 768 + (kk0) + lc1;                       \
            cp16(so, Ahg + ga2); cp16(so + 14336u, Alg + ga2);                  \
            cp16(so + 28672u, Whg + gb); cp16(so + 43008u, Wlg + gb);           \
            so = (stbase) + (uint32_t)(lr2 * LDA48 + lc2) * 2;                  \
            ga2 = (size_t)(m0 + lr2) * 768 + (kk0) + lc2;                       \
            gb  = (size_t)(n0 + lr2) * 768 + (kk0) + lc2;                       \
            cp16(so, Ahg + ga2); cp16(so + 14336u, Alg + ga2);                  \
            cp16(so + 28672u, Whg + gb); cp16(so + 43008u, Wlg + gb);           \
        }
        LD_CHUNK(s0, 0);
        CP_COMMIT();
    }
    for (int c = 0; c < 16; c++) {
        const int st = c & 1;
        if (c < 15) {
            const uint32_t stb = sb + (uint32_t)(st ^ 1) * 57344u;
            LD_CHUNK(stb, (c + 1) * 48);
            CP_COMMIT();
            CP_WAIT1();
        } else {
            CP_WAIT0();
        }
        __syncthreads();
        const uint32_t base = sb + (uint32_t)st * 57344u;
        #pragma unroll
        for (int ks = 0; ks < 3; ks++) {
            uint32_t ah[4][4], al[4][4];
            const int arow = wm + (lane & 7) + ((lane >> 3) & 1) * 8;
            const int acol = ks * 16 + (lane >> 4) * 8;
            #pragma unroll
            for (int mt = 0; mt < 4; mt++) {
                uint32_t off = (uint32_t)((arow + mt * 16) * LDA48 + acol) * 2;
                ldm_x4(ah[mt], base + off);
                ldm_x4(al[mt], base + 14336u + off);
            }
            const int brow = wn + ((lane >> 4) & 1) * 8 + (lane & 7);
            const int bcol = ks * 16 + ((lane >> 3) & 1) * 8;
            #pragma unroll
            for (int np = 0; np < 2; np++) {
                uint32_t off = (uint32_t)((brow + np * 16) * LDA48 + bcol) * 2;
                uint32_t bh4[4], bl4[4];
                ldm_x4(bh4, base + 28672u + off);
                ldm_x4(bl4, base + 43008u + off);
                #pragma unroll
                for (int mt = 0; mt < 4; mt++) {
                    mma_bf16(acc[mt][2 * np],     ah[mt], &bh4[0]);
                    mma_bf16(acc[mt][2 * np + 1], ah[mt], &bh4[2]);
                }
                #pragma unroll
                for (int mt = 0; mt < 4; mt++) {
                    mma_bf16(acc[mt][2 * np],     ah[mt], &bl4[0]);
                    mma_bf16(acc[mt][2 * np + 1], ah[mt], &bl4[2]);
                }
                #pragma unroll
                for (int mt = 0; mt < 4; mt++) {
                    mma_bf16(acc[mt][2 * np],     al[mt], &bh4[0]);
                    mma_bf16(acc[mt][2 * np + 1], al[mt], &bh4[2]);
                }
            }
        }
        __syncthreads();
    }
    #pragma unroll
    for (int mt = 0; mt < 4; mt++) {
        const int m = m0 + wm + mt * 16 + (lane >> 2);
        #pragma unroll
        for (int nt = 0; nt < 4; nt++) {
            const int n = n0 + wn + nt * 8 + (lane & 3) * 2;
            float2 bv = *(const float2*)&bias[n];
            float f0 = acc[mt][nt][0] + bv.x, f1 = acc[mt][nt][1] + bv.y;
            float f2 = acc[mt][nt][2] + bv.x, f3 = acc[mt][nt][3] + bv.y;
            if (FUSED3) {
                uint32_t hi, lo;
                split2(f0, f1, hi, lo);
                *(uint32_t*)&Ch[(size_t)m * 768 + n] = hi;
                *(uint32_t*)&Cl[(size_t)m * 768 + n] = lo;
                split2(f2, f3, hi, lo);
                *(uint32_t*)&Ch[(size_t)(m + 8) * 768 + n] = hi;
                *(uint32_t*)&Cl[(size_t)(m + 8) * 768 + n] = lo;
            } else {
                *(float2*)&Cf[(size_t)m * 768 + n]       = make_float2(f0, f1);
                *(float2*)&Cf[(size_t)(m + 8) * 768 + n] = make_float2(f2, f3);
            }
        }
    }
}

// =====================================================================
// scores_exp: E = exp(0.125*Q.K^T) masked for kt<=qt tiles, fp32 to
// attn; zero-fill kt>qt; atomic rowsums. x4-paired K fragments.
// =====================================================================
__global__ void __launch_bounds__(256)
scores_exp(const uint16_t* __restrict__ Qh, const uint16_t* __restrict__ Ql,
           const uint16_t* __restrict__ Kh, const uint16_t* __restrict__ Kl,
           float* __restrict__ attn, float* __restrict__ rs)
{
    const int qt = blockIdx.x, kt = blockIdx.y, bh = blockIdx.z;
    const int q0 = qt * 128, k0 = kt * 128;
    const int tid = threadIdx.x;

    if (kt > qt) {
        float4 z = make_float4(0.f, 0.f, 0.f, 0.f);
        float4* o4 = (float4*)(attn + ((size_t)bh * S_ + q0) * S_ + k0);
        #pragma unroll
        for (int i = 0; i < 16; i++) {
            int f = tid + i * 256;
            int r = f >> 5, c = f & 31;
            o4[(size_t)r * (S_ / 4) + c] = z;
        }
        return;
    }

    extern __shared__ __align__(16) char sm[];
    const uint32_t sb = smem_u32(sm);
    const int wid = tid >> 5, lane = tid & 31;
    const int b = bh / N_HEADS, h = bh % N_HEADS;
    const int wm = (wid & 1) * 64, wn = (wid >> 1) * 32;
    const size_t qbase = (size_t)(b * S_ + q0) * 768 + h * 64;
    const size_t kbase = (size_t)(b * S_ + k0) * 768 + h * 64;

    #pragma unroll
    for (int i = 0; i < 4; i++) {
        int f = tid + i * 256;
        int r = f >> 3, c8 = (f & 7) * 8;
        uint32_t so = sb + (uint32_t)(r * LDV + c8) * 2;
        size_t gq = qbase + (size_t)r * 768 + c8;
        size_t gk = kbase + (size_t)r * 768 + c8;
        cp16(so,          Qh + gq);
        cp16(so + 18432u, Ql + gq);
        cp16(so + 36864u, Kh + gk);
        cp16(so + 55296u, Kl + gk);
    }
    CP_COMMIT(); CP_WAIT0();
    __syncthreads();

    float acc[4][4][4] = {};
    #pragma unroll
    for (int ks = 0; ks < 4; ks++) {
        uint32_t ah[4][4], al[4][4];
        const int arow = wm + (lane & 7) + ((lane >> 3) & 1) * 8;
        const int acol = ks * 16 + (lane >> 4) * 8;
        #pragma unroll
        for (int mt = 0; mt < 4; mt++) {
            uint32_t off = (uint32_t)((arow + mt * 16) * LDV + acol) * 2;
            ldm_x4(ah[mt], sb + off);
            ldm_x4(al[mt], sb + 18432u + off);
        }
        const int brow = wn + ((lane >> 4) & 1) * 8 + (lane & 7);
        const int bcol = ks * 16 + ((lane >> 3) & 1) * 8;
        #pragma unroll
        for (int np = 0; np < 2; np++) {
            uint32_t off = (uint32_t)((brow + np * 16) * LDV + bcol) * 2;
            uint32_t bh4[4], bl4[4];
            ldm_x4(bh4, sb + 36864u + off);
            ldm_x4(bl4, sb + 55296u + off);
            #pragma unroll
            for (int mt = 0; mt < 4; mt++) {
                mma_bf16(acc[mt][2 * np],     ah[mt], &bh4[0]);
                mma_bf16(acc[mt][2 * np + 1], ah[mt], &bh4[2]);
            }
            #pragma unroll
            for (int mt = 0; mt < 4; mt++) {
                mma_bf16(acc[mt][2 * np],     ah[mt], &bl4[0]);
                mma_bf16(acc[mt][2 * np + 1], ah[mt], &bl4[2]);
            }
            #pragma unroll
            for (int mt = 0; mt < 4; mt++) {
                mma_bf16(acc[mt][2 * np],     al[mt], &bh4[0]);
                mma_bf16(acc[mt][2 * np + 1], al[mt], &bh4[2]);
            }
        }
    }

    // epilogue: masked exp, fp32 store, atomic rowsums
    #pragma unroll
    for (int mt = 0; mt < 4; mt++) {
        const int qr0 = q0 + wm + mt * 16 + (lane >> 2);
        const int qr1 = qr0 + 8;
        float rsum0 = 0.f, rsum1 = 0.f;
        #pragma unroll
        for (int nt = 0; nt < 4; nt++) {
            const int kcol = k0 + wn + nt * 8 + (lane & 3) * 2;
            float e0 = (kcol     <= qr0) ? __expf(acc[mt][nt][0] * 0.125f) : 0.f;
            float e1 = (kcol + 1 <= qr0) ? __expf(acc[mt][nt][1] * 0.125f) : 0.f;
            float e2 = (kcol     <= qr1) ? __expf(acc[mt][nt][2] * 0.125f) : 0.f;
            float e3 = (kcol + 1 <= qr1) ? __expf(acc[mt][nt][3] * 0.125f) : 0.f;
            rsum0 += e0 + e1;
            rsum1 += e2 + e3;
            *(float2*)&attn[((size_t)bh * S_ + qr0) * S_ + kcol] = make_float2(e0, e1);
            *(float2*)&attn[((size_t)bh * S_ + qr1) * S_ + kcol] = make_float2(e2, e3);
        }
        rsum0 += __shfl_xor_sync(0xffffffff, rsum0, 1);
        rsum0 += __shfl_xor_sync(0xffffffff, rsum0, 2);
        rsum1 += __shfl_xor_sync(0xffffffff, rsum1, 1);
        rsum1 += __shfl_xor_sync(0xffffffff, rsum1, 2);
        if ((lane & 3) == 0) {
            atomicAdd(&rs[(size_t)bh * S_ + qr0], rsum0);
            atomicAdd(&rs[(size_t)bh * S_ + qr1], rsum1);
        }
    }
}

// =====================================================================
// PV: reads E, normalizes, writes normalized attn back, MMAs En@V.
// Double-buffered P, triple-buffered V, x4.trans-paired V fragments.
// Dynamic smem: P 2x(hi+lo) 40960 | V 3x(hi+lo) 27648 | inv 512 = 69120
// =====================================================================
__global__ void __launch_bounds__(256)
pv_s(float* __restrict__ attn, const float* __restrict__ rs,
     const uint16_t* __restrict__ Vhg, const uint16_t* __restrict__ Vlg,
     uint16_t* __restrict__ Oh, uint16_t* __restrict__ Ol)
{
    extern __shared__ __align__(16) char sm[];
    const uint32_t sb = smem_u32(sm);
    float* inv_s = (float*)(sm + 68608);
    const int tid = threadIdx.x, wid = tid >> 5, lane = tid & 31;
    const int qt = gridDim.x - 1 - blockIdx.x;
    const int bh = blockIdx.y;
    const int b = bh / N_HEADS, h = bh % N_HEADS;
    const int q0 = qt * 128;
    const int wm = (wid & 3) * 32, wn = (wid >> 2) * 32;

    float* Arow = attn + ((size_t)bh * S_ + q0) * S_;
    const size_t vbase = (size_t)(b * S_) * 768 + h * 64;
    const int vr = tid >> 3, vc8 = (tid & 7) * 8;
    const uint32_t vso = (uint32_t)(vr * LDV + vc8) * 2;

    float acc[2][4][4] = {};
    const int n_chunks = 4 * (qt + 1);
    const int prow = tid >> 1, pc4 = (tid & 1) * 16;

    if (tid < 128)
        inv_s[tid] = 1.0f / rs[(size_t)bh * S_ + q0 + tid];
    {   // V chunk 0 -> buffer 0
        size_t gv = vbase + (size_t)vr * 768 + vc8;
        uint32_t vb0 = sb + 40960u;
        cp16(vb0 + vso,          Vhg + gv);
        cp16(vb0 + 4608u + vso,  Vlg + gv);
        CP_COMMIT();
    }
    float4 preg[4];
    #pragma unroll
    for (int j = 0; j < 4; j++)
        preg[j] = *(const float4*)&Arow[(size_t)prow * S_ + pc4 + j * 4];
    __syncthreads();                       // inv_s ready
    const float pinv = inv_s[prow];

    for (int c = 0; c < n_chunks; c++) {
        const int pst = c & 1;
        const int vst = c % 3;
        const int k0 = c * 32;
        const uint32_t pHb = sb + (uint32_t)pst * 20480u;
        const uint32_t pLb = pHb + 10240u;
        // stage normalized E(c) into P[pst] + write back to attn
        #pragma unroll
        for (int j = 0; j < 4; j++) {
            float4 t = preg[j];
            t.x *= pinv; t.y *= pinv; t.z *= pinv; t.w *= pinv;
            *(float4*)&Arow[(size_t)prow * S_ + k0 + pc4 + j * 4] = t;
            uint2 hi, lo;
            split4(t, hi, lo);
            uint32_t off = (uint32_t)(prow * LDA + pc4 + j * 4) * 2;
            *(uint2*)(sm + (pHb - sb) + off) = hi;
            *(uint2*)(sm + (pLb - sb) + off) = lo;
        }
        if (c + 1 < n_chunks) {    // V(c+1) -> buffer (c+1)%3
            size_t gv = vbase + (size_t)((c + 1) * 32 + vr) * 768 + vc8;
            uint32_t vbn = sb + 40960u + (uint32_t)((c + 1) % 3) * 9216u;
            cp16(vbn + vso,         Vhg + gv);
            cp16(vbn + 4608u + vso, Vlg + gv);
            CP_COMMIT();
            CP_WAIT1();
        } else {
            CP_WAIT0();
        }
        __syncthreads();
        if (c + 1 < n_chunks) {
            const int k0n = (c + 1) * 32;
            #pragma unroll
            for (int j = 0; j < 4; j++)
                preg[j] = *(const float4*)&Arow[(size_t)prow * S_ + k0n + pc4 + j * 4];
        }
        const uint32_t vHb = sb + 40960u + (uint32_t)vst * 9216u;
        const uint32_t vLb = vHb + 4608u;
        #pragma unroll
        for (int ks = 0; ks < 2; ks++) {
            uint32_t ph[2][4], pl[2][4];
            const int arow = wm + (lane & 7) + ((lane >> 3) & 1) * 8;
            const int acol = ks * 16 + (lane >> 4) * 8;
            #pragma unroll
            for (int mt = 0; mt < 2; mt++) {
                uint32_t off = (uint32_t)((arow + mt * 16) * LDA + acol) * 2;
                ldm_x4(ph[mt], pHb + off);
                ldm_x4(pl[mt], pLb + off);
            }
            const int krow = ks * 16 + ((lane >> 3) & 1) * 8 + (lane & 7);
            const int vcol = wn + ((lane >> 4) & 1) * 8;
            #pragma unroll
            for (int np = 0; np < 2; np++) {
                uint32_t off = (uint32_t)(krow * LDV + vcol + np * 16) * 2;
                uint32_t vh4[4], vl4[4];
                ldm_x4_trans(vh4, vHb + off);
                ldm_x4_trans(vl4, vLb + off);
                #pragma unroll
                for (int mt = 0; mt < 2; mt++) {
                    mma_bf16(acc[mt][2 * np],     ph[mt], &vh4[0]);
                    mma_bf16(acc[mt][2 * np + 1], ph[mt], &vh4[2]);
                }
                #pragma unroll
                for (int mt = 0; mt < 2; mt++) {
                    mma_bf16(acc[mt][2 * np],     ph[mt], &vl4[0]);
                    mma_bf16(acc[mt][2 * np + 1], ph[mt], &vl4[2]);
                }
                #pragma unroll
                for (int mt = 0; mt < 2; mt++) {
                    mma_bf16(acc[mt][2 * np],     pl[mt], &vh4[0]);
                    mma_bf16(acc[mt][2 * np + 1], pl[mt], &vh4[2]);
                }
            }
        }
        // no trailing barrier (P double-buffered, V triple-buffered)
    }
    #pragma unroll
    for (int mt = 0; mt < 2; mt++) {
        const int qrow = q0 + wm + mt * 16 + (lane >> 2);
        const size_t r0 = (size_t)(b * S_ + qrow) * 768 + h * 64;
        const size_t r1 = (size_t)(b * S_ + qrow + 8) * 768 + h * 64;
        #pragma unroll
        for (int nt = 0; nt < 4; nt++) {
            const int n = wn + nt * 8 + (lane & 3) * 2;
            uint32_t hi, lo;
            split2(acc[mt][nt][0], acc[mt][nt][1], hi, lo);
            *(uint32_t*)&Oh[r0 + n] = hi;
            *(uint32_t*)&Ol[r0 + n] = lo;
            split2(acc[mt][nt][2], acc[mt][nt][3], hi, lo);
            *(uint32_t*)&Oh[r1 + n] = hi;
            *(uint32_t*)&Ol[r1 + n] = lo;
        }
    }
}

// =====================================================================
// Residual + LayerNorm, float4, 192 threads.
// =====================================================================
__global__ void ln_kernel(const float* __restrict__ resid,
                          const float* __restrict__ P,
                          const float* __restrict__ gamma,
                          const float* __restrict__ beta,
                          float* __restrict__ out)
{
    const int m = blockIdx.x;
    const int tid = threadIdx.x;
    const int lane = tid & 31, wid = tid >> 5;
    __shared__ float red[6];

    const float4* r4 = (const float4*)(resid + (size_t)m * D_MODEL);
    const float4* p4 = (const float4*)(P + (size_t)m * D_MODEL);
    float4 a = r4[tid], b = p4[tid];
    float4 x = make_float4(a.x + b.x, a.y + b.y, a.z + b.z, a.w + b.w);

    float s = x.x + x.y + x.z + x.w;
    #pragma unroll
    for (int sh = 16; sh > 0; sh >>= 1)
        s += __shfl_xor_sync(0xffffffff, s, sh);
    if (lane == 0) red[wid] = s;
    __syncthreads();
    s = red[0] + red[1] + red[2] + red[3] + red[4] + red[5];
    const float mu = s * (1.0f / D_MODEL);
    __syncthreads();

    float4 d = make_float4(x.x - mu, x.y - mu, x.z - mu, x.w - mu);
    float v = d.x * d.x + d.y * d.y + d.z * d.z + d.w * d.w;
    #pragma unroll
    for (int sh = 16; sh > 0; sh >>= 1)
        v += __shfl_xor_sync(0xffffffff, v, sh);
    if (lane == 0) red[wid] = v;
    __syncthreads();
    v = red[0] + red[1] + red[2] + red[3] + red[4] + red[5];
    const float rstd = rsqrtf(v * (1.0f / D_MODEL) + LN_EPS);

    float4 g = ((const float4*)gamma)[tid];
    float4 be = ((const float4*)beta)[tid];
    float4 o = make_float4(d.x * rstd * g.x + be.x,
                           d.y * rstd * g.y + be.y,
                           d.z * rstd * g.z + be.z,
                           d.w * rstd * g.w + be.w);
    ((float4*)(out + (size_t)m * D_MODEL))[tid] = o;
}

// =====================================================================
extern "C" void kernel_launch(void* const* d_in, const int* in_sizes, int n_in,
                              void* d_out, int out_size)
{
    const float* q     = (const float*)d_in[0];
    const float* k     = (const float*)d_in[1];
    const float* v     = (const float*)d_in[2];
    const float* Wq    = (const float*)d_in[4];
    const float* bq    = (const float*)d_in[5];
    const float* Wk    = (const float*)d_in[6];
    const float* bk    = (const float*)d_in[7];
    const float* Wv    = (const float*)d_in[8];
    const float* bv    = (const float*)d_in[9];
    const float* Wo    = (const float*)d_in[10];
    const float* bo    = (const float*)d_in[11];
    const float* gamma = (const float*)d_in[12];
    const float* beta  = (const float*)d_in[13];

    float* out  = (float*)d_out;
    float* attn = out + (size_t)M_TOT * D_MODEL;

    uint16_t *inqh, *inql, *inkh, *inkl, *invh, *invl;
    uint16_t *wqh, *wql, *wkh, *wkl, *wvh, *wvl, *woh, *wol;
    uint16_t *Qh, *Ql, *Kh, *Kl, *Vh, *Vl, *Oh, *Ol;
    float *Pp, *rsp;
    cudaGetSymbolAddress((void**)&inqh, g_inqh); cudaGetSymbolAddress((void**)&inql, g_inql);
    cudaGetSymbolAddress((void**)&inkh, g_inkh); cudaGetSymbolAddress((void**)&inkl, g_inkl);
    cudaGetSymbolAddress((void**)&invh, g_invh); cudaGetSymbolAddress((void**)&invl, g_invl);
    cudaGetSymbolAddress((void**)&wqh, g_wqh); cudaGetSymbolAddress((void**)&wql, g_wql);
    cudaGetSymbolAddress((void**)&wkh, g_wkh); cudaGetSymbolAddress((void**)&wkl, g_wkl);
    cudaGetSymbolAddress((void**)&wvh, g_wvh); cudaGetSymbolAddress((void**)&wvl, g_wvl);
    cudaGetSymbolAddress((void**)&woh, g_woh); cudaGetSymbolAddress((void**)&wol, g_wol);
    cudaGetSymbolAddress((void**)&Qh, g_Qh); cudaGetSymbolAddress((void**)&Ql, g_Ql);
    cudaGetSymbolAddress((void**)&Kh, g_Kh); cudaGetSymbolAddress((void**)&Kl, g_Kl);
    cudaGetSymbolAddress((void**)&Vh, g_Vh); cudaGetSymbolAddress((void**)&Vl, g_Vl);
    cudaGetSymbolAddress((void**)&Oh, g_Oh); cudaGetSymbolAddress((void**)&Ol, g_Ol);
    cudaGetSymbolAddress((void**)&Pp, g_P);
    cudaGetSymbolAddress((void**)&rsp, g_rs);

    const int SMEM_GEMM   = 114688;
    const int SMEM_SCORES = 73728;
    const int SMEM_PV     = 69120;
    cudaFuncSetAttribute(gemm_s<true>,  cudaFuncAttributeMaxDynamicSharedMemorySize, SMEM_GEMM);
    cudaFuncSetAttribute(gemm_s<false>, cudaFuncAttributeMaxDynamicSharedMemorySize, SMEM_GEMM);
    cudaFuncSetAttribute(scores_exp,    cudaFuncAttributeMaxDynamicSharedMemorySize, SMEM_SCORES);
    cudaFuncSetAttribute(pv_s,          cudaFuncAttributeMaxDynamicSharedMemorySize, SMEM_PV);

    // fused pre-split of inputs (3 x 3072 blocks)
    SplitArgs sa_in;
    sa_in.in[0] = (const float4*)q; sa_in.hi[0] = (uint2*)inqh; sa_in.lo[0] = (uint2*)inql;
    sa_in.in[1] = (const float4*)k; sa_in.hi[1] = (uint2*)inkh; sa_in.lo[1] = (uint2*)inkl;
    sa_in.in[2] = (const float4*)v; sa_in.hi[2] = (uint2*)invh; sa_in.lo[2] = (uint2*)invl;
    sa_in.in[3] = nullptr; sa_in.hi[3] = nullptr; sa_in.lo[3] = nullptr;
    split_fused_kernel<<<dim3(3072, 3), 256>>>(sa_in, 3, nullptr, 0);

    // fused pre-split of weights + rowsum zeroing (z == 4)
    SplitArgs sa_w;
    sa_w.in[0] = (const float4*)Wq; sa_w.hi[0] = (uint2*)wqh; sa_w.lo[0] = (uint2*)wql;
    sa_w.in[1] = (const float4*)Wk; sa_w.hi[1] = (uint2*)wkh; sa_w.lo[1] = (uint2*)wkl;
    sa_w.in[2] = (const float4*)Wv; sa_w.hi[2] = (uint2*)wvh; sa_w.lo[2] = (uint2*)wvl;
    sa_w.in[3] = (const float4*)Wo; sa_w.hi[3] = (uint2*)woh; sa_w.lo[3] = (uint2*)wol;
    split_fused_kernel<<<dim3(576, 5), 256>>>(sa_w, 4, (float4*)rsp, 48);

    // fused QKV projections
    Gemm3Args ga;
    ga.Ah[0] = inqh; ga.Al[0] = inql; ga.Wh[0] = wqh; ga.Wl[0] = wql;
    ga.bias[0] = bq; ga.Ch[0] = Qh; ga.Cl[0] = Ql;
    ga.Ah[1] = inkh; ga.Al[1] = inkl; ga.Wh[1] = wkh; ga.Wl[1] = wkl;
    ga.bias[1] = bk; ga.Ch[1] = Kh; ga.Cl[1] = Kl;
    ga.Ah[2] = invh; ga.Al[2] = invl; ga.Wh[2] = wvh; ga.Wl[2] = wvl;
    ga.bias[2] = bv; ga.Ch[2] = Vh; ga.Cl[2] = Vl;
    dim3 gProj3(M_TOT / 128, D_MODEL / 128, 3);
    gemm_s<true><<<gProj3, 256, SMEM_GEMM>>>(ga, nullptr, nullptr, nullptr, nullptr,
                                             nullptr, nullptr);

    // scores + exp + rowsums (+ zero-fill of masked tiles)
    dim3 gScores(S_ / 128, S_ / 128, BH_);
    scores_exp<<<gScores, 256, SMEM_SCORES>>>(Qh, Ql, Kh, Kl, attn, rsp);

    // PV + in-place attn normalization
    dim3 gPV(S_ / 128, BH_);
    pv_s<<<gPV, 256, SMEM_PV>>>(attn, rsp, Vh, Vl, Oh, Ol);

    Gemm3Args ga_dummy = {};
    dim3 gProj(M_TOT / 128, D_MODEL / 128);
    gemm_s<false><<<gProj, 256, SMEM_GEMM>>>(ga_dummy, Oh, Ol, woh, wol, bo, Pp);

    ln_kernel<<<M_TOT, 192>>>(q, Pp, gamma, beta, out);
}

// round 15
// speedup vs baseline: 1.0660x; 1.0660x over previous
#include <cuda_runtime.h>
#include <cuda_bf16.h>
#include <math.h>
#include <stdint.h>

#define D_MODEL 768
#define N_HEADS 12
#define D_KH    64
#define B_      2
#define S_      2048
#define M_TOT   (B_ * S_)
#define BH_     (B_ * N_HEADS)
#define LN_EPS  1e-5f
#define NELEM   ((size_t)M_TOT * D_MODEL)
#define WELEM   ((size_t)D_MODEL * D_MODEL)

// ---------------- scratch (allocation-free: __device__ globals) ----------------
__device__ uint16_t g_inqh[NELEM], g_inql[NELEM];
__device__ uint16_t g_inkh[NELEM], g_inkl[NELEM];
__device__ uint16_t g_invh[NELEM], g_invl[NELEM];
__device__ uint16_t g_wqh[WELEM], g_wql[WELEM];
__device__ uint16_t g_wkh[WELEM], g_wkl[WELEM];
__device__ uint16_t g_wvh[WELEM], g_wvl[WELEM];
__device__ uint16_t g_woh[WELEM], g_wol[WELEM];
__device__ uint16_t g_Qh[NELEM], g_Ql[NELEM];
__device__ uint16_t g_Kh[NELEM], g_Kl[NELEM];
__device__ uint16_t g_Vh[NELEM], g_Vl[NELEM];
__device__ uint16_t g_Oh[NELEM], g_Ol[NELEM];
__device__ float    g_P[NELEM];
__device__ float    g_rs[(size_t)BH_ * S_];   // softmax row sums (unnormalized)

// ======================= helpers =======================
__device__ __forceinline__ uint32_t smem_u32(const void* p) {
    uint32_t a;
    asm("{ .reg .u64 t; cvta.to.shared.u64 t, %1; cvt.u32.u64 %0, t; }"
        : "=r"(a) : "l"(p));
    return a;
}
__device__ __forceinline__ void ldm_x4(uint32_t* r, uint32_t addr) {
    asm volatile("ldmatrix.sync.aligned.m8n8.x4.shared.b16 {%0,%1,%2,%3}, [%4];"
                 : "=r"(r[0]), "=r"(r[1]), "=r"(r[2]), "=r"(r[3]) : "r"(addr));
}
__device__ __forceinline__ void ldm_x4_trans(uint32_t* r, uint32_t addr) {
    asm volatile("ldmatrix.sync.aligned.m8n8.x4.trans.shared.b16 {%0,%1,%2,%3}, [%4];"
                 : "=r"(r[0]), "=r"(r[1]), "=r"(r[2]), "=r"(r[3]) : "r"(addr));
}
__device__ __forceinline__ void mma_bf16(float* c, const uint32_t* a, const uint32_t* b) {
    asm volatile(
        "mma.sync.aligned.m16n8k16.row.col.f32.bf16.bf16.f32 "
        "{%0,%1,%2,%3}, {%4,%5,%6,%7}, {%8,%9}, {%0,%1,%2,%3};"
        : "+f"(c[0]), "+f"(c[1]), "+f"(c[2]), "+f"(c[3])
        : "r"(a[0]), "r"(a[1]), "r"(a[2]), "r"(a[3]), "r"(b[0]), "r"(b[1]));
}
__device__ __forceinline__ void cp16(uint32_t s, const void* g) {
    asm volatile("cp.async.cg.shared.global [%0], [%1], 16;" :: "r"(s), "l"(g));
}
#define CP_COMMIT() asm volatile("cp.async.commit_group;")
#define CP_WAIT0()  asm volatile("cp.async.wait_group 0;")
#define CP_WAIT1()  asm volatile("cp.async.wait_group 1;")

__device__ __forceinline__ uint32_t pack2(__nv_bfloat16 a, __nv_bfloat16 b) {
    return ((uint32_t)__bfloat16_as_ushort(b) << 16) | (uint32_t)__bfloat16_as_ushort(a);
}
__device__ __forceinline__ void split4(float4 v, uint2& hi, uint2& lo) {
    __nv_bfloat16 h0 = __float2bfloat16(v.x), h1 = __float2bfloat16(v.y);
    __nv_bfloat16 h2 = __float2bfloat16(v.z), h3 = __float2bfloat16(v.w);
    hi = make_uint2(pack2(h0, h1), pack2(h2, h3));
    __nv_bfloat16 l0 = __float2bfloat16(v.x - __bfloat162float(h0));
    __nv_bfloat16 l1 = __float2bfloat16(v.y - __bfloat162float(h1));
    __nv_bfloat16 l2 = __float2bfloat16(v.z - __bfloat162float(h2));
    __nv_bfloat16 l3 = __float2bfloat16(v.w - __bfloat162float(h3));
    lo = make_uint2(pack2(l0, l1), pack2(l2, l3));
}
__device__ __forceinline__ void split2(float x, float y, uint32_t& hi, uint32_t& lo) {
    __nv_bfloat16 h0 = __float2bfloat16(x), h1 = __float2bfloat16(y);
    hi = pack2(h0, h1);
    lo = pack2(__float2bfloat16(x - __bfloat162float(h0)),
               __float2bfloat16(y - __bfloat162float(h1)));
}

// ======================= by-value arg structs (graph-safe) =======================
struct SplitArgs {
    const float4* in[4];
    uint2* hi[4];
    uint2* lo[4];
};
struct Gemm3Args {
    const uint16_t* Ah[3];
    const uint16_t* Al[3];
    const uint16_t* Wh[3];
    const uint16_t* Wl[3];
    const float*    bias[3];
    uint16_t*       Ch[3];
    uint16_t*       Cl[3];
};

// fused split; blockIdx.y == nsplit -> zero the rowsum buffer instead
__global__ void split_fused_kernel(SplitArgs a, int nsplit, float4* rs, int rs_blocks)
{
    const int z = blockIdx.y;
    if (z == nsplit) {
        if (blockIdx.x < rs_blocks)
            rs[blockIdx.x * 256 + threadIdx.x] = make_float4(0.f, 0.f, 0.f, 0.f);
        return;
    }
    int i = blockIdx.x * 256 + threadIdx.x;
    uint2 h, l;
    split4(a.in[z][i], h, l);
    a.hi[z][i] = h; a.lo[z][i] = l;
}

#define LDA 40
#define LDV 72

// =====================================================================
// GEMM (NT): C = A @ W^T + bias. K-chunk 32 (24 chunks), 2-stage
// cp.async pipeline, split-bf16, B fragments paired via ldmatrix.x4.
// smem 81920B -> 2 CTAs/SM.
// =====================================================================
template<bool FUSED3>
__global__ void __launch_bounds__(256)
gemm_s(Gemm3Args ga,
       const uint16_t* __restrict__ Ahg_, const uint16_t* __restrict__ Alg_,
       const uint16_t* __restrict__ Whg_, const uint16_t* __restrict__ Wlg_,
       const float* __restrict__ bias_, float* __restrict__ Cf)
{
    const uint16_t *Ahg, *Alg, *Whg, *Wlg;
    const float* bias;
    uint16_t *Ch = nullptr, *Cl = nullptr;
    if (FUSED3) {
        const int z = blockIdx.z;
        Ahg = ga.Ah[z]; Alg = ga.Al[z];
        Whg = ga.Wh[z]; Wlg = ga.Wl[z];
        bias = ga.bias[z]; Ch = ga.Ch[z]; Cl = ga.Cl[z];
    } else {
        Ahg = Ahg_; Alg = Alg_; Whg = Whg_; Wlg = Wlg_;
        bias = bias_;
    }

    extern __shared__ __align__(16) char sm[];
    const uint32_t sb = smem_u32(sm);
    const int tid = threadIdx.x, wid = tid >> 5, lane = tid & 31;
    const int m0 = blockIdx.x * 128, n0 = blockIdx.y * 128;
    const int wm = (wid & 1) * 64, wn = (wid >> 1) * 32;

    float acc[4][4][4] = {};
    {
        #pragma unroll
        for (int i = 0; i < 2; i++) {
            int f = tid + i * 256;
            int r = f >> 2, c8 = (f & 3) * 8;
            uint32_t so = sb + (uint32_t)(r * LDA + c8) * 2;
            size_t ga2 = (size_t)(m0 + r) * 768 + c8;
            size_t gb = (size_t)(n0 + r) * 768 + c8;
            cp16(so,          Ahg + ga2);
            cp16(so + 10240u, Alg + ga2);
            cp16(so + 20480u, Whg + gb);
            cp16(so + 30720u, Wlg + gb);
        }
        CP_COMMIT();
    }
    for (int c = 0; c < 24; c++) {
        const int st = c & 1;
        if (c < 23) {
            const int k0 = (c + 1) * 32;
            const uint32_t stb = sb + (uint32_t)(st ^ 1) * 40960u;
            #pragma unroll
            for (int i = 0; i < 2; i++) {
                int f = tid + i * 256;
                int r = f >> 2, c8 = (f & 3) * 8;
                uint32_t so = stb + (uint32_t)(r * LDA + c8) * 2;
                size_t ga2 = (size_t)(m0 + r) * 768 + k0 + c8;
                size_t gb = (size_t)(n0 + r) * 768 + k0 + c8;
                cp16(so,          Ahg + ga2);
                cp16(so + 10240u, Alg + ga2);
                cp16(so + 20480u, Whg + gb);
                cp16(so + 30720u, Wlg + gb);
            }
            CP_COMMIT();
            CP_WAIT1();
        } else {
            CP_WAIT0();
        }
        __syncthreads();
        const uint32_t base = sb + (uint32_t)st * 40960u;
        #pragma unroll
        for (int ks = 0; ks < 2; ks++) {
            uint32_t ah[4][4], al[4][4];
            const int arow = wm + (lane & 7) + ((lane >> 3) & 1) * 8;
            const int acol = ks * 16 + (lane >> 4) * 8;
            #pragma unroll
            for (int mt = 0; mt < 4; mt++) {
                uint32_t off = (uint32_t)((arow + mt * 16) * LDA + acol) * 2;
                ldm_x4(ah[mt], base + off);
                ldm_x4(al[mt], base + 10240u + off);
            }
            const int brow = wn + ((lane >> 4) & 1) * 8 + (lane & 7);
            const int bcol = ks * 16 + ((lane >> 3) & 1) * 8;
            #pragma unroll
            for (int np = 0; np < 2; np++) {
                uint32_t off = (uint32_t)((brow + np * 16) * LDA + bcol) * 2;
                uint32_t bh4[4], bl4[4];
                ldm_x4(bh4, base + 20480u + off);
                ldm_x4(bl4, base + 30720u + off);
                #pragma unroll
                for (int mt = 0; mt < 4; mt++) {
                    mma_bf16(acc[mt][2 * np],     ah[mt], &bh4[0]);
                    mma_bf16(acc[mt][2 * np + 1], ah[mt], &bh4[2]);
                }
                #pragma unroll
                for (int mt = 0; mt < 4; mt++) {
                    mma_bf16(acc[mt][2 * np],     ah[mt], &bl4[0]);
                    mma_bf16(acc[mt][2 * np + 1], ah[mt], &bl4[2]);
                }
                #pragma unroll
                for (int mt = 0; mt < 4; mt++) {
                    mma_bf16(acc[mt][2 * np],     al[mt], &bh4[0]);
                    mma_bf16(acc[mt][2 * np + 1], al[mt], &bh4[2]);
                }
            }
        }
        __syncthreads();
    }
    #pragma unroll
    for (int mt = 0; mt < 4; mt++) {
        const int m = m0 + wm + mt * 16 + (lane >> 2);
        #pragma unroll
        for (int nt = 0; nt < 4; nt++) {
            const int n = n0 + wn + nt * 8 + (lane & 3) * 2;
            float2 bv = *(const float2*)&bias[n];
            float f0 = acc[mt][nt][0] + bv.x, f1 = acc[mt][nt][1] + bv.y;
            float f2 = acc[mt][nt][2] + bv.x, f3 = acc[mt][nt][3] + bv.y;
            if (FUSED3) {
                uint32_t hi, lo;
                split2(f0, f1, hi, lo);
                *(uint32_t*)&Ch[(size_t)m * 768 + n] = hi;
                *(uint32_t*)&Cl[(size_t)m * 768 + n] = lo;
                split2(f2, f3, hi, lo);
                *(uint32_t*)&Ch[(size_t)(m + 8) * 768 + n] = hi;
                *(uint32_t*)&Cl[(size_t)(m + 8) * 768 + n] = lo;
            } else {
                *(float2*)&Cf[(size_t)m * 768 + n]       = make_float2(f0, f1);
                *(float2*)&Cf[(size_t)(m + 8) * 768 + n] = make_float2(f2, f3);
            }
        }
    }
}

// =====================================================================
// scores_exp: E = exp(0.125*Q.K^T) masked for kt<=qt tiles, fp32 to
// attn; zero-fill kt>qt; atomic rowsums. x4-paired K fragments.
// =====================================================================
__global__ void __launch_bounds__(256)
scores_exp(const uint16_t* __restrict__ Qh, const uint16_t* __restrict__ Ql,
           const uint16_t* __restrict__ Kh, const uint16_t* __restrict__ Kl,
           float* __restrict__ attn, float* __restrict__ rs)
{
    const int qt = blockIdx.x, kt = blockIdx.y, bh = blockIdx.z;
    const int q0 = qt * 128, k0 = kt * 128;
    const int tid = threadIdx.x;

    if (kt > qt) {
        float4 z = make_float4(0.f, 0.f, 0.f, 0.f);
        float4* o4 = (float4*)(attn + ((size_t)bh * S_ + q0) * S_ + k0);
        #pragma unroll
        for (int i = 0; i < 16; i++) {
            int f = tid + i * 256;
            int r = f >> 5, c = f & 31;
            o4[(size_t)r * (S_ / 4) + c] = z;
        }
        return;
    }

    extern __shared__ __align__(16) char sm[];
    const uint32_t sb = smem_u32(sm);
    const int wid = tid >> 5, lane = tid & 31;
    const int b = bh / N_HEADS, h = bh % N_HEADS;
    const int wm = (wid & 1) * 64, wn = (wid >> 1) * 32;
    const size_t qbase = (size_t)(b * S_ + q0) * 768 + h * 64;
    const size_t kbase = (size_t)(b * S_ + k0) * 768 + h * 64;

    #pragma unroll
    for (int i = 0; i < 4; i++) {
        int f = tid + i * 256;
        int r = f >> 3, c8 = (f & 7) * 8;
        uint32_t so = sb + (uint32_t)(r * LDV + c8) * 2;
        size_t gq = qbase + (size_t)r * 768 + c8;
        size_t gk = kbase + (size_t)r * 768 + c8;
        cp16(so,          Qh + gq);
        cp16(so + 18432u, Ql + gq);
        cp16(so + 36864u, Kh + gk);
        cp16(so + 55296u, Kl + gk);
    }
    CP_COMMIT(); CP_WAIT0();
    __syncthreads();

    float acc[4][4][4] = {};
    #pragma unroll
    for (int ks = 0; ks < 4; ks++) {
        uint32_t ah[4][4], al[4][4];
        const int arow = wm + (lane & 7) + ((lane >> 3) & 1) * 8;
        const int acol = ks * 16 + (lane >> 4) * 8;
        #pragma unroll
        for (int mt = 0; mt < 4; mt++) {
            uint32_t off = (uint32_t)((arow + mt * 16) * LDV + acol) * 2;
            ldm_x4(ah[mt], sb + off);
            ldm_x4(al[mt], sb + 18432u + off);
        }
        const int brow = wn + ((lane >> 4) & 1) * 8 + (lane & 7);
        const int bcol = ks * 16 + ((lane >> 3) & 1) * 8;
        #pragma unroll
        for (int np = 0; np < 2; np++) {
            uint32_t off = (uint32_t)((brow + np * 16) * LDV + bcol) * 2;
            uint32_t bh4[4], bl4[4];
            ldm_x4(bh4, sb + 36864u + off);
            ldm_x4(bl4, sb + 55296u + off);
            #pragma unroll
            for (int mt = 0; mt < 4; mt++) {
                mma_bf16(acc[mt][2 * np],     ah[mt], &bh4[0]);
                mma_bf16(acc[mt][2 * np + 1], ah[mt], &bh4[2]);
            }
            #pragma unroll
            for (int mt = 0; mt < 4; mt++) {
                mma_bf16(acc[mt][2 * np],     ah[mt], &bl4[0]);
                mma_bf16(acc[mt][2 * np + 1], ah[mt], &bl4[2]);
            }
            #pragma unroll
            for (int mt = 0; mt < 4; mt++) {
                mma_bf16(acc[mt][2 * np],     al[mt], &bh4[0]);
                mma_bf16(acc[mt][2 * np + 1], al[mt], &bh4[2]);
            }
        }
    }

    // epilogue: masked exp, fp32 store, atomic rowsums
    #pragma unroll
    for (int mt = 0; mt < 4; mt++) {
        const int qr0 = q0 + wm + mt * 16 + (lane >> 2);
        const int qr1 = qr0 + 8;
        float rsum0 = 0.f, rsum1 = 0.f;
        #pragma unroll
        for (int nt = 0; nt < 4; nt++) {
            const int kcol = k0 + wn + nt * 8 + (lane & 3) * 2;
            float e0 = (kcol     <= qr0) ? __expf(acc[mt][nt][0] * 0.125f) : 0.f;
            float e1 = (kcol + 1 <= qr0) ? __expf(acc[mt][nt][1] * 0.125f) : 0.f;
            float e2 = (kcol     <= qr1) ? __expf(acc[mt][nt][2] * 0.125f) : 0.f;
            float e3 = (kcol + 1 <= qr1) ? __expf(acc[mt][nt][3] * 0.125f) : 0.f;
            rsum0 += e0 + e1;
            rsum1 += e2 + e3;
            *(float2*)&attn[((size_t)bh * S_ + qr0) * S_ + kcol] = make_float2(e0, e1);
            *(float2*)&attn[((size_t)bh * S_ + qr1) * S_ + kcol] = make_float2(e2, e3);
        }
        rsum0 += __shfl_xor_sync(0xffffffff, rsum0, 1);
        rsum0 += __shfl_xor_sync(0xffffffff, rsum0, 2);
        rsum1 += __shfl_xor_sync(0xffffffff, rsum1, 1);
        rsum1 += __shfl_xor_sync(0xffffffff, rsum1, 2);
        if ((lane & 3) == 0) {
            atomicAdd(&rs[(size_t)bh * S_ + qr0], rsum0);
            atomicAdd(&rs[(size_t)bh * S_ + qr1], rsum1);
        }
    }
}

// =====================================================================
// PV: reads E, normalizes, writes normalized attn back, MMAs En@V.
// Double-buffered P, triple-buffered V, x4.trans-paired V fragments.
// Dynamic smem: P 2x(hi+lo) 40960 | V 3x(hi+lo) 27648 | inv 512 = 69120
// =====================================================================
__global__ void __launch_bounds__(256)
pv_s(float* __restrict__ attn, const float* __restrict__ rs,
     const uint16_t* __restrict__ Vhg, const uint16_t* __restrict__ Vlg,
     uint16_t* __restrict__ Oh, uint16_t* __restrict__ Ol)
{
    extern __shared__ __align__(16) char sm[];
    const uint32_t sb = smem_u32(sm);
    float* inv_s = (float*)(sm + 68608);
    const int tid = threadIdx.x, wid = tid >> 5, lane = tid & 31;
    const int qt = gridDim.x - 1 - blockIdx.x;
    const int bh = blockIdx.y;
    const int b = bh / N_HEADS, h = bh % N_HEADS;
    const int q0 = qt * 128;
    const int wm = (wid & 3) * 32, wn = (wid >> 2) * 32;

    float* Arow = attn + ((size_t)bh * S_ + q0) * S_;
    const size_t vbase = (size_t)(b * S_) * 768 + h * 64;
    const int vr = tid >> 3, vc8 = (tid & 7) * 8;
    const uint32_t vso = (uint32_t)(vr * LDV + vc8) * 2;

    float acc[2][4][4] = {};
    const int n_chunks = 4 * (qt + 1);
    const int prow = tid >> 1, pc4 = (tid & 1) * 16;

    if (tid < 128)
        inv_s[tid] = 1.0f / rs[(size_t)bh * S_ + q0 + tid];
    {   // V chunk 0 -> buffer 0
        size_t gv = vbase + (size_t)vr * 768 + vc8;
        uint32_t vb0 = sb + 40960u;
        cp16(vb0 + vso,          Vhg + gv);
        cp16(vb0 + 4608u + vso,  Vlg + gv);
        CP_COMMIT();
    }
    float4 preg[4];
    #pragma unroll
    for (int j = 0; j < 4; j++)
        preg[j] = *(const float4*)&Arow[(size_t)prow * S_ + pc4 + j * 4];
    __syncthreads();                       // inv_s ready
    const float pinv = inv_s[prow];

    for (int c = 0; c < n_chunks; c++) {
        const int pst = c & 1;
        const int vst = c % 3;
        const int k0 = c * 32;
        const uint32_t pHb = sb + (uint32_t)pst * 20480u;
        const uint32_t pLb = pHb + 10240u;
        // stage normalized E(c) into P[pst] + write back to attn
        #pragma unroll
        for (int j = 0; j < 4; j++) {
            float4 t = preg[j];
            t.x *= pinv; t.y *= pinv; t.z *= pinv; t.w *= pinv;
            *(float4*)&Arow[(size_t)prow * S_ + k0 + pc4 + j * 4] = t;
            uint2 hi, lo;
            split4(t, hi, lo);
            uint32_t off = (uint32_t)(prow * LDA + pc4 + j * 4) * 2;
            *(uint2*)(sm + (pHb - sb) + off) = hi;
            *(uint2*)(sm + (pLb - sb) + off) = lo;
        }
        if (c + 1 < n_chunks) {    // V(c+1) -> buffer (c+1)%3
            size_t gv = vbase + (size_t)((c + 1) * 32 + vr) * 768 + vc8;
            uint32_t vbn = sb + 40960u + (uint32_t)((c + 1) % 3) * 9216u;
            cp16(vbn + vso,         Vhg + gv);
            cp16(vbn + 4608u + vso, Vlg + gv);
            CP_COMMIT();
            CP_WAIT1();
        } else {
            CP_WAIT0();
        }
        __syncthreads();
        if (c + 1 < n_chunks) {
            const int k0n = (c + 1) * 32;
            #pragma unroll
            for (int j = 0; j < 4; j++)
                preg[j] = *(const float4*)&Arow[(size_t)prow * S_ + k0n + pc4 + j * 4];
        }
        const uint32_t vHb = sb + 40960u + (uint32_t)vst * 9216u;
        const uint32_t vLb = vHb + 4608u;
        #pragma unroll
        for (int ks = 0; ks < 2; ks++) {
            uint32_t ph[2][4], pl[2][4];
            const int arow = wm + (lane & 7) + ((lane >> 3) & 1) * 8;
            const int acol = ks * 16 + (lane >> 4) * 8;
            #pragma unroll
            for (int mt = 0; mt < 2; mt++) {
                uint32_t off = (uint32_t)((arow + mt * 16) * LDA + acol) * 2;
                ldm_x4(ph[mt], pHb + off);
                ldm_x4(pl[mt], pLb + off);
            }
            const int krow = ks * 16 + ((lane >> 3) & 1) * 8 + (lane & 7);
            const int vcol = wn + ((lane >> 4) & 1) * 8;
            #pragma unroll
            for (int np = 0; np < 2; np++) {
                uint32_t off = (uint32_t)(krow * LDV + vcol + np * 16) * 2;
                uint32_t vh4[4], vl4[4];
                ldm_x4_trans(vh4, vHb + off);
                ldm_x4_trans(vl4, vLb + off);
                #pragma unroll
                for (int mt = 0; mt < 2; mt++) {
                    mma_bf16(acc[mt][2 * np],     ph[mt], &vh4[0]);
                    mma_bf16(acc[mt][2 * np + 1], ph[mt], &vh4[2]);
                }
                #pragma unroll
                for (int mt = 0; mt < 2; mt++) {
                    mma_bf16(acc[mt][2 * np],     ph[mt], &vl4[0]);
                    mma_bf16(acc[mt][2 * np + 1], ph[mt], &vl4[2]);
                }
                #pragma unroll
                for (int mt = 0; mt < 2; mt++) {
                    mma_bf16(acc[mt][2 * np],     pl[mt], &vh4[0]);
                    mma_bf16(acc[mt][2 * np + 1], pl[mt], &vh4[2]);
                }
            }
        }
        // no trailing barrier (P double-buffered, V triple-buffered)
    }
    #pragma unroll
    for (int mt = 0; mt < 2; mt++) {
        const int qrow = q0 + wm + mt * 16 + (lane >> 2);
        const size_t r0 = (size_t)(b * S_ + qrow) * 768 + h * 64;
        const size_t r1 = (size_t)(b * S_ + qrow + 8) * 768 + h * 64;
        #pragma unroll
        for (int nt = 0; nt < 4; nt++) {
            const int n = wn + nt * 8 + (lane & 3) * 2;
            uint32_t hi, lo;
            split2(acc[mt][nt][0], acc[mt][nt][1], hi, lo);
            *(uint32_t*)&Oh[r0 + n] = hi;
            *(uint32_t*)&Ol[r0 + n] = lo;
            split2(acc[mt][nt][2], acc[mt][nt][3], hi, lo);
            *(uint32_t*)&Oh[r1 + n] = hi;
            *(uint32_t*)&Ol[r1 + n] = lo;
        }
    }
}

// =====================================================================
// Residual + LayerNorm, float4, 192 threads.
// =====================================================================
__global__ void ln_kernel(const float* __restrict__ resid,
                          const float* __restrict__ P,
                          const float* __restrict__ gamma,
                          const float* __restrict__ beta,
                          float* __restrict__ out)
{
    const int m = blockIdx.x;
    const int tid = threadIdx.x;
    const int lane = tid & 31, wid = tid >> 5;
    __shared__ float red[6];

    const float4* r4 = (const float4*)(resid + (size_t)m * D_MODEL);
    const float4* p4 = (const float4*)(P + (size_t)m * D_MODEL);
    float4 a = r4[tid], b = p4[tid];
    float4 x = make_float4(a.x + b.x, a.y + b.y, a.z + b.z, a.w + b.w);

    float s = x.x + x.y + x.z + x.w;
    #pragma unroll
    for (int sh = 16; sh > 0; sh >>= 1)
        s += __shfl_xor_sync(0xffffffff, s, sh);
    if (lane == 0) red[wid] = s;
    __syncthreads();
    s = red[0] + red[1] + red[2] + red[3] + red[4] + red[5];
    const float mu = s * (1.0f / D_MODEL);
    __syncthreads();

    float4 d = make_float4(x.x - mu, x.y - mu, x.z - mu, x.w - mu);
    float v = d.x * d.x + d.y * d.y + d.z * d.z + d.w * d.w;
    #pragma unroll
    for (int sh = 16; sh > 0; sh >>= 1)
        v += __shfl_xor_sync(0xffffffff, v, sh);
    if (lane == 0) red[wid] = v;
    __syncthreads();
    v = red[0] + red[1] + red[2] + red[3] + red[4] + red[5];
    const float rstd = rsqrtf(v * (1.0f / D_MODEL) + LN_EPS);

    float4 g = ((const float4*)gamma)[tid];
    float4 be = ((const float4*)beta)[tid];
    float4 o = make_float4(d.x * rstd * g.x + be.x,
                           d.y * rstd * g.y + be.y,
                           d.z * rstd * g.z + be.z,
                           d.w * rstd * g.w + be.w);
    ((float4*)(out + (size_t)m * D_MODEL))[tid] = o;
}

// =====================================================================
extern "C" void kernel_launch(void* const* d_in, const int* in_sizes, int n_in,
                              void* d_out, int out_size)
{
    const float* q     = (const float*)d_in[0];
    const float* k     = (const float*)d_in[1];
    const float* v     = (const float*)d_in[2];
    const float* Wq    = (const float*)d_in[4];
    const float* bq    = (const float*)d_in[5];
    const float* Wk    = (const float*)d_in[6];
    const float* bk    = (const float*)d_in[7];
    const float* Wv    = (const float*)d_in[8];
    const float* bv    = (const float*)d_in[9];
    const float* Wo    = (const float*)d_in[10];
    const float* bo    = (const float*)d_in[11];
    const float* gamma = (const float*)d_in[12];
    const float* beta  = (const float*)d_in[13];

    float* out  = (float*)d_out;
    float* attn = out + (size_t)M_TOT * D_MODEL;

    uint16_t *inqh, *inql, *inkh, *inkl, *invh, *invl;
    uint16_t *wqh, *wql, *wkh, *wkl, *wvh, *wvl, *woh, *wol;
    uint16_t *Qh, *Ql, *Kh, *Kl, *Vh, *Vl, *Oh, *Ol;
    float *Pp, *rsp;
    cudaGetSymbolAddress((void**)&inqh, g_inqh); cudaGetSymbolAddress((void**)&inql, g_inql);
    cudaGetSymbolAddress((void**)&inkh, g_inkh); cudaGetSymbolAddress((void**)&inkl, g_inkl);
    cudaGetSymbolAddress((void**)&invh, g_invh); cudaGetSymbolAddress((void**)&invl, g_invl);
    cudaGetSymbolAddress((void**)&wqh, g_wqh); cudaGetSymbolAddress((void**)&wql, g_wql);
    cudaGetSymbolAddress((void**)&wkh, g_wkh); cudaGetSymbolAddress((void**)&wkl, g_wkl);
    cudaGetSymbolAddress((void**)&wvh, g_wvh); cudaGetSymbolAddress((void**)&wvl, g_wvl);
    cudaGetSymbolAddress((void**)&woh, g_woh); cudaGetSymbolAddress((void**)&wol, g_wol);
    cudaGetSymbolAddress((void**)&Qh, g_Qh); cudaGetSymbolAddress((void**)&Ql, g_Ql);
    cudaGetSymbolAddress((void**)&Kh, g_Kh); cudaGetSymbolAddress((void**)&Kl, g_Kl);
    cudaGetSymbolAddress((void**)&Vh, g_Vh); cudaGetSymbolAddress((void**)&Vl, g_Vl);
    cudaGetSymbolAddress((void**)&Oh, g_Oh); cudaGetSymbolAddress((void**)&Ol, g_Ol);
    cudaGetSymbolAddress((void**)&Pp, g_P);
    cudaGetSymbolAddress((void**)&rsp, g_rs);

    const int SMEM_GEMM   = 81920;
    const int SMEM_SCORES = 73728;
    const int SMEM_PV     = 69120;
    cudaFuncSetAttribute(gemm_s<true>,  cudaFuncAttributeMaxDynamicSharedMemorySize, SMEM_GEMM);
    cudaFuncSetAttribute(gemm_s<false>, cudaFuncAttributeMaxDynamicSharedMemorySize, SMEM_GEMM);
    cudaFuncSetAttribute(scores_exp,    cudaFuncAttributeMaxDynamicSharedMemorySize, SMEM_SCORES);
    cudaFuncSetAttribute(pv_s,          cudaFuncAttributeMaxDynamicSharedMemorySize, SMEM_PV);

    // fused pre-split of inputs (3 x 3072 blocks)
    SplitArgs sa_in;
    sa_in.in[0] = (const float4*)q; sa_in.hi[0] = (uint2*)inqh; sa_in.lo[0] = (uint2*)inql;
    sa_in.in[1] = (const float4*)k; sa_in.hi[1] = (uint2*)inkh; sa_in.lo[1] = (uint2*)inkl;
    sa_in.in[2] = (const float4*)v; sa_in.hi[2] = (uint2*)invh; sa_in.lo[2] = (uint2*)invl;
    sa_in.in[3] = nullptr; sa_in.hi[3] = nullptr; sa_in.lo[3] = nullptr;
    split_fused_kernel<<<dim3(3072, 3), 256>>>(sa_in, 3, nullptr, 0);

    // fused pre-split of weights + rowsum zeroing (z == 4)
    SplitArgs sa_w;
    sa_w.in[0] = (const float4*)Wq; sa_w.hi[0] = (uint2*)wqh; sa_w.lo[0] = (uint2*)wql;
    sa_w.in[1] = (const float4*)Wk; sa_w.hi[1] = (uint2*)wkh; sa_w.lo[1] = (uint2*)wkl;
    sa_w.in[2] = (const float4*)Wv; sa_w.hi[2] = (uint2*)wvh; sa_w.lo[2] = (uint2*)wvl;
    sa_w.in[3] = (const float4*)Wo; sa_w.hi[3] = (uint2*)woh; sa_w.lo[3] = (uint2*)wol;
    split_fused_kernel<<<dim3(576, 5), 256>>>(sa_w, 4, (float4*)rsp, 48);

    // fused QKV projections
    Gemm3Args ga;
    ga.Ah[0] = inqh; ga.Al[0] = inql; ga.Wh[0] = wqh; ga.Wl[0] = wql;
    ga.bias[0] = bq; ga.Ch[0] = Qh; ga.Cl[0] = Ql;
    ga.Ah[1] = inkh; ga.Al[1] = inkl; ga.Wh[1] = wkh; ga.Wl[1] = wkl;
    ga.bias[1] = bk; ga.Ch[1] = Kh; ga.Cl[1] = Kl;
    ga.Ah[2] = invh; ga.Al[2] = invl; ga.Wh[2] = wvh; ga.Wl[2] = wvl;
    ga.bias[2] = bv; ga.Ch[2] = Vh; ga.Cl[2] = Vl;
    dim3 gProj3(M_TOT / 128, D_MODEL / 128, 3);
    gemm_s<true><<<gProj3, 256, SMEM_GEMM>>>(ga, nullptr, nullptr, nullptr, nullptr,
                                             nullptr, nullptr);

    // scores + exp + rowsums (+ zero-fill of masked tiles)
    dim3 gScores(S_ / 128, S_ / 128, BH_);
    scores_exp<<<gScores, 256, SMEM_SCORES>>>(Qh, Ql, Kh, Kl, attn, rsp);

    // PV + in-place attn normalization
    dim3 gPV(S_ / 128, BH_);
    pv_s<<<gPV, 256, SMEM_PV>>>(attn, rsp, Vh, Vl, Oh, Ol);

    Gemm3Args ga_dummy = {};
    dim3 gProj(M_TOT / 128, D_MODEL / 128);
    gemm_s<false><<<gProj, 256, SMEM_GEMM>>>(ga_dummy, Oh, Ol, woh, wol, bo, Pp);

    ln_kernel<<<M_TOT, 192>>>(q, Pp, gamma, beta, out);
}